// round 2
// baseline (speedup 1.0000x reference)
#include <cuda_runtime.h>
#include <math.h>

// Problem constants (fixed by setup_inputs)
#define BB 8
#define SS 4096
#define DD 512
#define NCHUNK 64
#define SROWS (SS / NCHUNK)   // 64 rows per block
#define PP 98                 // sampled partitions
#define KMAXP 6
#define MAXPART 100
#define MASK_ELEMS (PP * KMAXP * DD)   // 301056

// Scratch (no allocations allowed -> __device__ globals)
__device__ float g_partE[NCHUNK * BB * DD];   // per-chunk partial sum exp(x)
__device__ float g_partT[NCHUNK * BB * DD];   // per-chunk partial sum x*exp(x)
__device__ float g_sumE[BB * DD];
__device__ float g_sumT[BB * DD];
__device__ float g_Hfull[BB];                 // per-batch full-flatten entropy
__device__ float g_hsingle[BB];               // per-batch sum_d H_sd
__device__ float g_hpk[BB * PP];              // per (b,p) sum_k H_pk
__device__ int   g_esize;                     // detected mask element size (1 or 4)

// ---------------------------------------------------------------------------
// Kernel 0: detect part_masks element size.
// If masks are 1-byte bools (density ~1/6), bytes at offset 4*i+1 within the
// first MASK_ELEMS bytes are frequently nonzero. If elements are int32(0/1)
// or float32(0.0/1.0), byte offset ≡1 (mod 4) is ALWAYS zero
// (int32 1 = 01 00 00 00; float 1.0 = 00 00 80 3f).
// Reading MASK_ELEMS bytes is in-bounds for every candidate dtype.
// ---------------------------------------------------------------------------
__global__ void k0_detect(const unsigned char* __restrict__ m) {
    __shared__ int found;
    if (threadIdx.x == 0) found = 0;
    __syncthreads();
    int local = 0;
    for (int i = threadIdx.x; i < MASK_ELEMS / 4; i += 256)
        local |= m[4 * i + 1];
    if (local) found = 1;
    __syncthreads();
    if (threadIdx.x == 0) g_esize = found ? 1 : 4;
}

// ---------------------------------------------------------------------------
// Kernel 1: streaming pass over x. grid = (NCHUNK, B), 256 threads.
// Thread t owns d = 2t, 2t+1 (float2 loads, fully coalesced 2KB rows).
// Accumulates SumE/SumT partials for its 64 s-rows.
// ---------------------------------------------------------------------------
__global__ void __launch_bounds__(256) k1_stream(const float* __restrict__ x) {
    const int chunk = blockIdx.x;
    const int b     = blockIdx.y;
    const int t     = threadIdx.x;

    const float2* xp = reinterpret_cast<const float2*>(
        x + ((size_t)b * SS + (size_t)chunk * SROWS) * DD) + t;

    float e0 = 0.f, e1 = 0.f, t0 = 0.f, t1 = 0.f;
    #pragma unroll 8
    for (int i = 0; i < SROWS; i++) {
        float2 v = xp[(size_t)i * (DD / 2)];
        float p0 = __expf(v.x);
        float p1 = __expf(v.y);
        e0 += p0;
        e1 += p1;
        t0 = fmaf(p0, v.x, t0);
        t1 = fmaf(p1, v.y, t1);
    }

    const int base = (chunk * BB + b) * DD;  // chunk-major for coalesced k2 reads
    reinterpret_cast<float2*>(g_partE + base)[t] = make_float2(e0, e1);
    reinterpret_cast<float2*>(g_partT + base)[t] = make_float2(t0, t1);
}

// ---------------------------------------------------------------------------
// Kernel 2: reduce chunks -> final SumE/SumT per (b,d); per-batch entropies.
// grid = B, 512 threads (one per d).
// ---------------------------------------------------------------------------
__global__ void __launch_bounds__(512) k2_reduce() {
    const int b = blockIdx.x;
    const int d = threadIdx.x;

    float e = 0.f, t = 0.f;
    #pragma unroll 8
    for (int c = 0; c < NCHUNK; c++) {
        const int idx = (c * BB + b) * DD + d;
        e += g_partE[idx];
        t += g_partT[idx];
    }
    g_sumE[b * DD + d] = e;
    g_sumT[b * DD + d] = t;

    // singleton entropy for this (b,d)
    float h = logf(e) - t / e;

    // block-reduce three sums: sum_d H_sd, sum_d SumE, sum_d SumT
    float se = e, st = t, sh = h;
    #pragma unroll
    for (int o = 16; o > 0; o >>= 1) {
        se += __shfl_down_sync(0xffffffffu, se, o);
        st += __shfl_down_sync(0xffffffffu, st, o);
        sh += __shfl_down_sync(0xffffffffu, sh, o);
    }
    __shared__ float wE[16], wT[16], wH[16];
    const int w = d >> 5, l = d & 31;
    if (l == 0) { wE[w] = se; wT[w] = st; wH[w] = sh; }
    __syncthreads();
    if (d < 32) {
        se = (d < 16) ? wE[d] : 0.f;
        st = (d < 16) ? wT[d] : 0.f;
        sh = (d < 16) ? wH[d] : 0.f;
        #pragma unroll
        for (int o = 8; o > 0; o >>= 1) {
            se += __shfl_down_sync(0xffffffffu, se, o);
            st += __shfl_down_sync(0xffffffffu, st, o);
            sh += __shfl_down_sync(0xffffffffu, sh, o);
        }
        if (d == 0) {
            g_hsingle[b] = sh;
            g_Hfull[b]   = logf(se) - st / se;  // full-flatten entropy
        }
    }
}

// ---------------------------------------------------------------------------
// Kernel 3: sampled partitions. grid = (P, B), 256 threads.
// Each thread bins its 2 d's into K<=6 groups; warp+shared reduce; thread 0
// computes sum_k (log Z_k - T_k/Z_k) over non-empty bins.
// Mask element size comes from g_esize (nonzero test works for bool/int/float).
// ---------------------------------------------------------------------------
__global__ void __launch_bounds__(256) k3_parts(const void* __restrict__ masks_raw) {
    const int p = blockIdx.x;
    const int b = blockIdx.y;
    const int t = threadIdx.x;
    const int esize = g_esize;
    const unsigned char* m8  = (const unsigned char*)masks_raw;
    const unsigned int*  m32 = (const unsigned int*)masks_raw;

    float zk[KMAXP], tk[KMAXP];
    #pragma unroll
    for (int k = 0; k < KMAXP; k++) { zk[k] = 0.f; tk[k] = 0.f; }

    #pragma unroll
    for (int rep = 0; rep < 2; rep++) {
        const int d = t + rep * 256;
        const float e  = g_sumE[b * DD + d];
        const float tt = g_sumT[b * DD + d];
        #pragma unroll
        for (int k = 0; k < KMAXP; k++) {
            const int idx = (p * KMAXP + k) * DD + d;
            const bool mv = (esize == 1) ? (m8[idx] != 0) : (m32[idx] != 0u);
            if (mv) {
                zk[k] += e;
                tk[k] += tt;
                break;  // each d belongs to exactly one part
            }
        }
    }

    // warp reduce all 12 accumulators
    #pragma unroll
    for (int o = 16; o > 0; o >>= 1) {
        #pragma unroll
        for (int k = 0; k < KMAXP; k++) {
            zk[k] += __shfl_down_sync(0xffffffffu, zk[k], o);
            tk[k] += __shfl_down_sync(0xffffffffu, tk[k], o);
        }
    }
    __shared__ float sz[8][KMAXP], st[8][KMAXP];
    const int w = t >> 5, l = t & 31;
    if (l == 0) {
        #pragma unroll
        for (int k = 0; k < KMAXP; k++) { sz[w][k] = zk[k]; st[w][k] = tk[k]; }
    }
    __syncthreads();
    if (t == 0) {
        float hsum = 0.f;
        #pragma unroll
        for (int k = 0; k < KMAXP; k++) {
            float Z = 0.f, T = 0.f;
            #pragma unroll
            for (int ww = 0; ww < 8; ww++) { Z += sz[ww][k]; T += st[ww][k]; }
            if (Z > 0.f) hsum += logf(Z) - T / Z;  // empty bin -> contributes 0
        }
        g_hpk[b * PP + p] = hsum;
    }
}

// ---------------------------------------------------------------------------
// Kernel 4: combine 100 parts, min over weighted, MLP head. 1 block, 128 thr.
// ---------------------------------------------------------------------------
__global__ void __launch_bounds__(128) k4_final(
    const float* __restrict__ es,  const float* __restrict__ iw,
    const float* __restrict__ W1,  const float* __restrict__ b1,
    const float* __restrict__ W2,  const float* __restrict__ b2,
    const float* __restrict__ W3,  const float* __restrict__ b3,
    float* __restrict__ out)
{
    __shared__ float sh_min[128];
    __shared__ float sh_es[128];
    const int t = threadIdx.x;

    // entropy_scales mean (parallel partial sums)
    float se = 0.f;
    for (int i = t; i < DD; i += 128) se += es[i];
    sh_es[t] = se;

    // weighted h_parts
    float wv = INFINITY;
    if (t < MAXPART) {
        float h;
        if (t == 0) {
            float s = 0.f;
            for (int bb = 0; bb < BB; bb++) s += g_Hfull[bb];
            h = s / (float)BB;                         // h_whole
        } else if (t == 1) {
            float s = 0.f;
            for (int bb = 0; bb < BB; bb++) s += g_hsingle[bb];
            h = s / (float)BB;                         // h_single
        } else {
            float s = 0.f;
            for (int bb = 0; bb < BB; bb++) s += g_hpk[bb * PP + (t - 2)];
            h = s / (float)BB;                         // h_sampled[t-2]
        }
        const float sg = 1.f / (1.f + expf(-iw[t]));
        wv = h * sg;
    }
    sh_min[t] = wv;
    __syncthreads();

    #pragma unroll
    for (int o = 64; o > 0; o >>= 1) {
        if (t < o) {
            sh_min[t] = fminf(sh_min[t], sh_min[t + o]);
            sh_es[t] += sh_es[t + o];
        }
        __syncthreads();
    }

    if (t == 0) {
        const float es_mean = sh_es[0] / (float)DD;
        float s = 0.f;
        for (int bb = 0; bb < BB; bb++) s += g_Hfull[bb];
        const float h_whole = s / (float)BB;

        const float raw_phi = es_mean * h_whole - sh_min[0];
        float z = raw_phi * 0.1f;
        z = fminf(fmaxf(z, 0.f), 1.f);

        float h1v[32];
        #pragma unroll
        for (int j = 0; j < 32; j++) {
            float v = fmaf(z, W1[j], b1[j]);   // W1 is (32,1)
            h1v[j] = fmaxf(v, 0.f);
        }
        float h2v[16];
        #pragma unroll
        for (int i = 0; i < 16; i++) {
            float a = b2[i];
            #pragma unroll
            for (int j = 0; j < 32; j++) a = fmaf(W2[i * 32 + j], h1v[j], a);
            h2v[i] = fmaxf(a, 0.f);
        }
        float o3 = b3[0];
        #pragma unroll
        for (int i = 0; i < 16; i++) o3 = fmaf(W3[i], h2v[i], o3);

        out[0] = 1.f / (1.f + expf(-o3));
    }
}

// ---------------------------------------------------------------------------
extern "C" void kernel_launch(void* const* d_in, const int* in_sizes, int n_in,
                              void* d_out, int out_size) {
    const float* x  = (const float*)d_in[0];
    const float* es = (const float*)d_in[1];
    const float* iw = (const float*)d_in[2];
    const float* W1 = (const float*)d_in[3];
    const float* b1 = (const float*)d_in[4];
    const float* W2 = (const float*)d_in[5];
    const float* b2 = (const float*)d_in[6];
    const float* W3 = (const float*)d_in[7];
    const float* b3 = (const float*)d_in[8];
    const void*  masks = (const void*)d_in[9];

    k0_detect<<<1, 256>>>((const unsigned char*)masks);
    k1_stream<<<dim3(NCHUNK, BB), 256>>>(x);
    k2_reduce<<<BB, 512>>>();
    k3_parts<<<dim3(PP, BB), 256>>>(masks);
    k4_final<<<1, 128>>>(es, iw, W1, b1, W2, b2, W3, b3, (float*)d_out);
}

// round 3
// speedup vs baseline: 1.1151x; 1.1151x over previous
#include <cuda_runtime.h>
#include <math.h>

// Problem constants (fixed by setup_inputs)
#define BB 8
#define SS 4096
#define DD 512
#define NCHUNK 64
#define SROWS (SS / NCHUNK)   // 64 rows per k1 block
#define PP 98                 // sampled partitions
#define KMAXP 6
#define MAXPART 100
#define MASK_ELEMS (PP * KMAXP * DD)   // 301056

// Scratch (no allocations allowed -> __device__ globals)
__device__ float g_partE[NCHUNK * BB * DD];
__device__ float g_partT[NCHUNK * BB * DD];
__device__ float g_sumE[BB * DD];
__device__ float g_sumT[BB * DD];
__device__ float g_Hfull[BB];
__device__ float g_hsingle[BB];
__device__ float g_hpk[BB * PP];
__device__ int   g_found;                        // 1 => masks are 1-byte elements
__device__ unsigned char g_assign[PP * DD];      // part index (0..5) per (p,d)

// ---------------------------------------------------------------------------
// k0z: zero detection flag (runs every call; OR-accumulation is idempotent
// and deterministic across replays).
// ---------------------------------------------------------------------------
__global__ void k0z() { g_found = 0; }

// ---------------------------------------------------------------------------
// k0: parallel mask element-size detection. If elements are 1-byte bools,
// byte offset ≡1 (mod 4) within the first MASK_ELEMS bytes is frequently
// nonzero; for int32(0/1) or float32(0.0/1.0) that byte is always zero
// (int32 1 = 01 00 00 00 ; 1.0f = 00 00 80 3f). Word-wise test of byte1.
// ---------------------------------------------------------------------------
__global__ void __launch_bounds__(256) k0_detect(const unsigned int* __restrict__ m) {
    unsigned int v = 0;
    const int n = MASK_ELEMS / 4;            // 75264 words — in-bounds for all dtypes
    for (int j = blockIdx.x * 256 + threadIdx.x; j < n; j += gridDim.x * 256)
        v |= m[j] & 0x0000FF00u;
    if (__syncthreads_or(v != 0)) {
        if (threadIdx.x == 0) atomicOr(&g_found, 1);
    }
}

// ---------------------------------------------------------------------------
// ka: precompute per-(p,d) part assignment. grid = 98, 512 threads.
// Six independent loads, branchless select (last-match from high k downward;
// each d belongs to exactly one part, so order is irrelevant).
// ---------------------------------------------------------------------------
__global__ void __launch_bounds__(512) ka_assign(const void* __restrict__ masks_raw) {
    const int p = blockIdx.x;
    const int d = threadIdx.x;
    const bool isU8 = (g_found != 0);
    const unsigned char* m8  = (const unsigned char*)masks_raw;
    const unsigned int*  m32 = (const unsigned int*)masks_raw;

    int a = 0;
    #pragma unroll
    for (int k = KMAXP - 1; k >= 0; k--) {
        const int idx = (p * KMAXP + k) * DD + d;
        const bool mv = isU8 ? (m8[idx] != 0) : (m32[idx] != 0u);
        if (mv) a = k;
    }
    g_assign[p * DD + d] = (unsigned char)a;
}

// ---------------------------------------------------------------------------
// k1: streaming pass over x. grid = (NCHUNK, B), 128 threads.
// Thread t owns 4 d's (float4), fully coalesced 2KB rows, 64 rows per block.
// ---------------------------------------------------------------------------
__global__ void __launch_bounds__(128) k1_stream(const float* __restrict__ x) {
    const int chunk = blockIdx.x;
    const int b     = blockIdx.y;
    const int t     = threadIdx.x;

    const float4* xp = reinterpret_cast<const float4*>(
        x + ((size_t)b * SS + (size_t)chunk * SROWS) * DD) + t;

    float e0 = 0.f, e1 = 0.f, e2 = 0.f, e3 = 0.f;
    float t0 = 0.f, t1 = 0.f, t2 = 0.f, t3 = 0.f;
    #pragma unroll 8
    for (int i = 0; i < SROWS; i++) {
        float4 v = xp[(size_t)i * (DD / 4)];
        float p0 = __expf(v.x), p1 = __expf(v.y), p2 = __expf(v.z), p3 = __expf(v.w);
        e0 += p0; e1 += p1; e2 += p2; e3 += p3;
        t0 = fmaf(p0, v.x, t0);
        t1 = fmaf(p1, v.y, t1);
        t2 = fmaf(p2, v.z, t2);
        t3 = fmaf(p3, v.w, t3);
    }

    const int base = (chunk * BB + b) * DD;  // chunk-major for coalesced k2 reads
    reinterpret_cast<float4*>(g_partE + base)[t] = make_float4(e0, e1, e2, e3);
    reinterpret_cast<float4*>(g_partT + base)[t] = make_float4(t0, t1, t2, t3);
}

// ---------------------------------------------------------------------------
// k2: reduce chunks -> final SumE/SumT per (b,d); per-batch entropies.
// grid = B, 512 threads (one per d).
// ---------------------------------------------------------------------------
__global__ void __launch_bounds__(512) k2_reduce() {
    const int b = blockIdx.x;
    const int d = threadIdx.x;

    float e = 0.f, t = 0.f;
    #pragma unroll 8
    for (int c = 0; c < NCHUNK; c++) {
        const int idx = (c * BB + b) * DD + d;
        e += g_partE[idx];
        t += g_partT[idx];
    }
    g_sumE[b * DD + d] = e;
    g_sumT[b * DD + d] = t;

    float h = logf(e) - t / e;   // singleton entropy for this (b,d)

    float se = e, st = t, sh = h;
    #pragma unroll
    for (int o = 16; o > 0; o >>= 1) {
        se += __shfl_down_sync(0xffffffffu, se, o);
        st += __shfl_down_sync(0xffffffffu, st, o);
        sh += __shfl_down_sync(0xffffffffu, sh, o);
    }
    __shared__ float wE[16], wT[16], wH[16];
    const int w = d >> 5, l = d & 31;
    if (l == 0) { wE[w] = se; wT[w] = st; wH[w] = sh; }
    __syncthreads();
    if (d < 32) {
        se = (d < 16) ? wE[d] : 0.f;
        st = (d < 16) ? wT[d] : 0.f;
        sh = (d < 16) ? wH[d] : 0.f;
        #pragma unroll
        for (int o = 8; o > 0; o >>= 1) {
            se += __shfl_down_sync(0xffffffffu, se, o);
            st += __shfl_down_sync(0xffffffffu, st, o);
            sh += __shfl_down_sync(0xffffffffu, sh, o);
        }
        if (d == 0) {
            g_hsingle[b] = sh;
            g_Hfull[b]   = logf(se) - st / se;
        }
    }
}

// ---------------------------------------------------------------------------
// k3: sampled partitions, branchless. grid = (P, B), 128 threads x 4 d's.
// One uchar4 assign load + two float4 E/T loads per thread; select-add into
// 12 registers; warp + cross-warp reduce; thread 0 sums group entropies.
// ---------------------------------------------------------------------------
__global__ void __launch_bounds__(128) k3_parts() {
    const int p = blockIdx.x;
    const int b = blockIdx.y;
    const int t = threadIdx.x;

    const uchar4 a4 = reinterpret_cast<const uchar4*>(g_assign + p * DD)[t];
    const float4 e4 = reinterpret_cast<const float4*>(g_sumE + b * DD)[t];
    const float4 t4 = reinterpret_cast<const float4*>(g_sumT + b * DD)[t];

    float zk[KMAXP], tk[KMAXP];
    #pragma unroll
    for (int k = 0; k < KMAXP; k++) {
        zk[k] = (a4.x == k ? e4.x : 0.f) + (a4.y == k ? e4.y : 0.f)
              + (a4.z == k ? e4.z : 0.f) + (a4.w == k ? e4.w : 0.f);
        tk[k] = (a4.x == k ? t4.x : 0.f) + (a4.y == k ? t4.y : 0.f)
              + (a4.z == k ? t4.z : 0.f) + (a4.w == k ? t4.w : 0.f);
    }

    #pragma unroll
    for (int o = 16; o > 0; o >>= 1) {
        #pragma unroll
        for (int k = 0; k < KMAXP; k++) {
            zk[k] += __shfl_down_sync(0xffffffffu, zk[k], o);
            tk[k] += __shfl_down_sync(0xffffffffu, tk[k], o);
        }
    }
    __shared__ float sz[4][KMAXP], st[4][KMAXP];
    const int w = t >> 5, l = t & 31;
    if (l == 0) {
        #pragma unroll
        for (int k = 0; k < KMAXP; k++) { sz[w][k] = zk[k]; st[w][k] = tk[k]; }
    }
    __syncthreads();
    if (t == 0) {
        float hsum = 0.f;
        #pragma unroll
        for (int k = 0; k < KMAXP; k++) {
            float Z = sz[0][k] + sz[1][k] + sz[2][k] + sz[3][k];
            float T = st[0][k] + st[1][k] + st[2][k] + st[3][k];
            if (Z > 0.f) hsum += logf(Z) - T / Z;   // empty bin -> 0
        }
        g_hpk[b * PP + p] = hsum;
    }
}

// ---------------------------------------------------------------------------
// k4: combine 100 parts, min over weighted, MLP head. 1 block, 128 thr.
// ---------------------------------------------------------------------------
__global__ void __launch_bounds__(128) k4_final(
    const float* __restrict__ es,  const float* __restrict__ iw,
    const float* __restrict__ W1,  const float* __restrict__ b1,
    const float* __restrict__ W2,  const float* __restrict__ b2,
    const float* __restrict__ W3,  const float* __restrict__ b3,
    float* __restrict__ out)
{
    __shared__ float sh_min[128];
    __shared__ float sh_es[128];
    const int t = threadIdx.x;

    float se = 0.f;
    for (int i = t; i < DD; i += 128) se += es[i];
    sh_es[t] = se;

    float wv = INFINITY;
    if (t < MAXPART) {
        float h;
        if (t == 0) {
            float s = 0.f;
            for (int bb = 0; bb < BB; bb++) s += g_Hfull[bb];
            h = s / (float)BB;
        } else if (t == 1) {
            float s = 0.f;
            for (int bb = 0; bb < BB; bb++) s += g_hsingle[bb];
            h = s / (float)BB;
        } else {
            float s = 0.f;
            for (int bb = 0; bb < BB; bb++) s += g_hpk[bb * PP + (t - 2)];
            h = s / (float)BB;
        }
        const float sg = 1.f / (1.f + expf(-iw[t]));
        wv = h * sg;
    }
    sh_min[t] = wv;
    __syncthreads();

    #pragma unroll
    for (int o = 64; o > 0; o >>= 1) {
        if (t < o) {
            sh_min[t] = fminf(sh_min[t], sh_min[t + o]);
            sh_es[t] += sh_es[t + o];
        }
        __syncthreads();
    }

    if (t == 0) {
        const float es_mean = sh_es[0] / (float)DD;
        float s = 0.f;
        for (int bb = 0; bb < BB; bb++) s += g_Hfull[bb];
        const float h_whole = s / (float)BB;

        const float raw_phi = es_mean * h_whole - sh_min[0];
        float z = raw_phi * 0.1f;
        z = fminf(fmaxf(z, 0.f), 1.f);

        float h1v[32];
        #pragma unroll
        for (int j = 0; j < 32; j++) h1v[j] = fmaxf(fmaf(z, W1[j], b1[j]), 0.f);
        float h2v[16];
        #pragma unroll
        for (int i = 0; i < 16; i++) {
            float a = b2[i];
            #pragma unroll
            for (int j = 0; j < 32; j++) a = fmaf(W2[i * 32 + j], h1v[j], a);
            h2v[i] = fmaxf(a, 0.f);
        }
        float o3 = b3[0];
        #pragma unroll
        for (int i = 0; i < 16; i++) o3 = fmaf(W3[i], h2v[i], o3);

        out[0] = 1.f / (1.f + expf(-o3));
    }
}

// ---------------------------------------------------------------------------
extern "C" void kernel_launch(void* const* d_in, const int* in_sizes, int n_in,
                              void* d_out, int out_size) {
    const float* x  = (const float*)d_in[0];
    const float* es = (const float*)d_in[1];
    const float* iw = (const float*)d_in[2];
    const float* W1 = (const float*)d_in[3];
    const float* b1 = (const float*)d_in[4];
    const float* W2 = (const float*)d_in[5];
    const float* b2 = (const float*)d_in[6];
    const float* W3 = (const float*)d_in[7];
    const float* b3 = (const float*)d_in[8];
    const void*  masks = (const void*)d_in[9];

    k0z<<<1, 1>>>();
    k0_detect<<<148, 256>>>((const unsigned int*)masks);
    ka_assign<<<PP, 512>>>(masks);
    k1_stream<<<dim3(NCHUNK, BB), 128>>>(x);
    k2_reduce<<<BB, 512>>>();
    k3_parts<<<dim3(PP, BB), 128>>>();
    k4_final<<<1, 128>>>(es, iw, W1, b1, W2, b2, W3, b3, (float*)d_out);
}

// round 4
// speedup vs baseline: 1.3656x; 1.2247x over previous
#include <cuda_runtime.h>
#include <math.h>

// Problem constants (fixed by setup_inputs)
#define BB 8
#define SS 4096
#define DD 512
#define NCHUNK 128
#define SROWS (SS / NCHUNK)   // 32 rows per k1 block
#define NGRP 16               // k2a chunk groups (8 chunks each)
#define PP 98                 // sampled partitions
#define KMAXP 6
#define MAXPART 100
#define MASK_WORDS_PER_P (KMAXP * DD / 4)   // 768 words in u8-byte terms

// Scratch (no allocations allowed -> __device__ globals)
__device__ float g_partE[NCHUNK * BB * DD];   // 2 MB
__device__ float g_partT[NCHUNK * BB * DD];
__device__ float g_p2E[NGRP * BB * DD];       // 256 KB
__device__ float g_p2T[NGRP * BB * DD];
__device__ float g_sumE[BB * DD];
__device__ float g_sumT[BB * DD];
__device__ float g_Hfull[BB];
__device__ float g_hsingle[BB];
__device__ float g_hpk[BB * PP];
__device__ unsigned char g_assign[PP * DD];   // part index (0..5) per (p,d)

// ---------------------------------------------------------------------------
// ka: per-(p,d) part assignment WITH per-block mask-dtype detection.
// Detection: scan words covering u8-byte range [p*3072,(p+1)*3072) and test
// byte1 (offset ≡1 mod 4). u8 layout: each d≡1 (mod 4) has exactly one k with
// mask=1 -> exactly 128 nonzero bytes at those offsets (guaranteed hit).
// u32 layout (int32/float32 0/1): byte1 of every element is 0 (guaranteed
// miss), and the scanned range lies inside the first 301056 bytes -> in
// bounds for all candidate dtypes. Deterministic, no global state.
// ---------------------------------------------------------------------------
__global__ void __launch_bounds__(512) ka_assign(const void* __restrict__ masks_raw) {
    const int p = blockIdx.x;
    const int d = threadIdx.x;
    const unsigned int*  mw  = (const unsigned int*)masks_raw;
    const unsigned char* m8  = (const unsigned char*)masks_raw;

    unsigned int v = 0;
    #pragma unroll
    for (int j = d; j < MASK_WORDS_PER_P; j += 512)
        v |= mw[p * MASK_WORDS_PER_P + j] & 0x0000FF00u;
    const bool isU8 = (__syncthreads_or(v != 0) != 0);

    int a = 0;
    #pragma unroll
    for (int k = KMAXP - 1; k >= 0; k--) {
        const int idx = (p * KMAXP + k) * DD + d;
        const bool mv = isU8 ? (m8[idx] != 0) : (mw[idx] != 0u);
        if (mv) a = k;
    }
    g_assign[p * DD + d] = (unsigned char)a;
}

// ---------------------------------------------------------------------------
// k1: streaming pass over x. grid = (NCHUNK, B), 256 threads (float2/thread).
// 1024 blocks x 8 warps = 8192 warps (~55/SM) to saturate HBM.
// ---------------------------------------------------------------------------
__global__ void __launch_bounds__(256) k1_stream(const float* __restrict__ x) {
    const int chunk = blockIdx.x;
    const int b     = blockIdx.y;
    const int t     = threadIdx.x;

    const float2* xp = reinterpret_cast<const float2*>(
        x + ((size_t)b * SS + (size_t)chunk * SROWS) * DD) + t;

    float e0 = 0.f, e1 = 0.f, t0 = 0.f, t1 = 0.f;
    #pragma unroll 8
    for (int i = 0; i < SROWS; i++) {
        float2 v = xp[(size_t)i * (DD / 2)];
        float p0 = __expf(v.x);
        float p1 = __expf(v.y);
        e0 += p0;
        e1 += p1;
        t0 = fmaf(p0, v.x, t0);
        t1 = fmaf(p1, v.y, t1);
    }

    const int base = (chunk * BB + b) * DD;  // chunk-major for coalesced k2a reads
    reinterpret_cast<float2*>(g_partE + base)[t] = make_float2(e0, e1);
    reinterpret_cast<float2*>(g_partT + base)[t] = make_float2(t0, t1);
}

// ---------------------------------------------------------------------------
// k2a: reduce 128 chunks -> 16 group-partials. grid = (NGRP, B), 512 threads.
// ---------------------------------------------------------------------------
__global__ void __launch_bounds__(512) k2a_reduce() {
    const int g = blockIdx.x;
    const int b = blockIdx.y;
    const int d = threadIdx.x;

    float e = 0.f, t = 0.f;
    #pragma unroll
    for (int i = 0; i < NCHUNK / NGRP; i++) {
        const int idx = ((g * (NCHUNK / NGRP) + i) * BB + b) * DD + d;
        e += g_partE[idx];
        t += g_partT[idx];
    }
    g_p2E[(g * BB + b) * DD + d] = e;
    g_p2T[(g * BB + b) * DD + d] = t;
}

// ---------------------------------------------------------------------------
// k2b: final per-(b,d) sums + per-batch entropies. grid = B, 512 threads.
// ---------------------------------------------------------------------------
__global__ void __launch_bounds__(512) k2b_reduce() {
    const int b = blockIdx.x;
    const int d = threadIdx.x;

    float e = 0.f, t = 0.f;
    #pragma unroll
    for (int g = 0; g < NGRP; g++) {
        const int idx = (g * BB + b) * DD + d;
        e += g_p2E[idx];
        t += g_p2T[idx];
    }
    g_sumE[b * DD + d] = e;
    g_sumT[b * DD + d] = t;

    float h = logf(e) - t / e;   // singleton entropy for this (b,d)

    float se = e, st = t, sh = h;
    #pragma unroll
    for (int o = 16; o > 0; o >>= 1) {
        se += __shfl_down_sync(0xffffffffu, se, o);
        st += __shfl_down_sync(0xffffffffu, st, o);
        sh += __shfl_down_sync(0xffffffffu, sh, o);
    }
    __shared__ float wE[16], wT[16], wH[16];
    const int w = d >> 5, l = d & 31;
    if (l == 0) { wE[w] = se; wT[w] = st; wH[w] = sh; }
    __syncthreads();
    if (d < 32) {
        se = (d < 16) ? wE[d] : 0.f;
        st = (d < 16) ? wT[d] : 0.f;
        sh = (d < 16) ? wH[d] : 0.f;
        #pragma unroll
        for (int o = 8; o > 0; o >>= 1) {
            se += __shfl_down_sync(0xffffffffu, se, o);
            st += __shfl_down_sync(0xffffffffu, st, o);
            sh += __shfl_down_sync(0xffffffffu, sh, o);
        }
        if (d == 0) {
            g_hsingle[b] = sh;
            g_Hfull[b]   = logf(se) - st / se;
        }
    }
}

// ---------------------------------------------------------------------------
// k3: sampled partitions, branchless. grid = (P, B), 128 threads x 4 d's.
// ---------------------------------------------------------------------------
__global__ void __launch_bounds__(128) k3_parts() {
    const int p = blockIdx.x;
    const int b = blockIdx.y;
    const int t = threadIdx.x;

    const uchar4 a4 = reinterpret_cast<const uchar4*>(g_assign + p * DD)[t];
    const float4 e4 = reinterpret_cast<const float4*>(g_sumE + b * DD)[t];
    const float4 t4 = reinterpret_cast<const float4*>(g_sumT + b * DD)[t];

    float zk[KMAXP], tk[KMAXP];
    #pragma unroll
    for (int k = 0; k < KMAXP; k++) {
        zk[k] = (a4.x == k ? e4.x : 0.f) + (a4.y == k ? e4.y : 0.f)
              + (a4.z == k ? e4.z : 0.f) + (a4.w == k ? e4.w : 0.f);
        tk[k] = (a4.x == k ? t4.x : 0.f) + (a4.y == k ? t4.y : 0.f)
              + (a4.z == k ? t4.z : 0.f) + (a4.w == k ? t4.w : 0.f);
    }

    #pragma unroll
    for (int o = 16; o > 0; o >>= 1) {
        #pragma unroll
        for (int k = 0; k < KMAXP; k++) {
            zk[k] += __shfl_down_sync(0xffffffffu, zk[k], o);
            tk[k] += __shfl_down_sync(0xffffffffu, tk[k], o);
        }
    }
    __shared__ float sz[4][KMAXP], st[4][KMAXP];
    const int w = t >> 5, l = t & 31;
    if (l == 0) {
        #pragma unroll
        for (int k = 0; k < KMAXP; k++) { sz[w][k] = zk[k]; st[w][k] = tk[k]; }
    }
    __syncthreads();
    if (t == 0) {
        float hsum = 0.f;
        #pragma unroll
        for (int k = 0; k < KMAXP; k++) {
            float Z = sz[0][k] + sz[1][k] + sz[2][k] + sz[3][k];
            float T = st[0][k] + st[1][k] + st[2][k] + st[3][k];
            if (Z > 0.f) hsum += logf(Z) - T / Z;   // empty bin -> 0
        }
        g_hpk[b * PP + p] = hsum;
    }
}

// ---------------------------------------------------------------------------
// k4: combine 100 parts, min over weighted, MLP head. 1 block, 128 thr.
// ---------------------------------------------------------------------------
__global__ void __launch_bounds__(128) k4_final(
    const float* __restrict__ es,  const float* __restrict__ iw,
    const float* __restrict__ W1,  const float* __restrict__ b1,
    const float* __restrict__ W2,  const float* __restrict__ b2,
    const float* __restrict__ W3,  const float* __restrict__ b3,
    float* __restrict__ out)
{
    __shared__ float sh_min[128];
    __shared__ float sh_es[128];
    const int t = threadIdx.x;

    float se = 0.f;
    for (int i = t; i < DD; i += 128) se += es[i];
    sh_es[t] = se;

    float wv = INFINITY;
    if (t < MAXPART) {
        float h;
        if (t == 0) {
            float s = 0.f;
            for (int bb = 0; bb < BB; bb++) s += g_Hfull[bb];
            h = s / (float)BB;
        } else if (t == 1) {
            float s = 0.f;
            for (int bb = 0; bb < BB; bb++) s += g_hsingle[bb];
            h = s / (float)BB;
        } else {
            float s = 0.f;
            for (int bb = 0; bb < BB; bb++) s += g_hpk[bb * PP + (t - 2)];
            h = s / (float)BB;
        }
        const float sg = 1.f / (1.f + expf(-iw[t]));
        wv = h * sg;
    }
    sh_min[t] = wv;
    __syncthreads();

    #pragma unroll
    for (int o = 64; o > 0; o >>= 1) {
        if (t < o) {
            sh_min[t] = fminf(sh_min[t], sh_min[t + o]);
            sh_es[t] += sh_es[t + o];
        }
        __syncthreads();
    }

    if (t == 0) {
        const float es_mean = sh_es[0] / (float)DD;
        float s = 0.f;
        for (int bb = 0; bb < BB; bb++) s += g_Hfull[bb];
        const float h_whole = s / (float)BB;

        const float raw_phi = es_mean * h_whole - sh_min[0];
        float z = raw_phi * 0.1f;
        z = fminf(fmaxf(z, 0.f), 1.f);

        float h1v[32];
        #pragma unroll
        for (int j = 0; j < 32; j++) h1v[j] = fmaxf(fmaf(z, W1[j], b1[j]), 0.f);
        float h2v[16];
        #pragma unroll
        for (int i = 0; i < 16; i++) {
            float a = b2[i];
            #pragma unroll
            for (int j = 0; j < 32; j++) a = fmaf(W2[i * 32 + j], h1v[j], a);
            h2v[i] = fmaxf(a, 0.f);
        }
        float o3 = b3[0];
        #pragma unroll
        for (int i = 0; i < 16; i++) o3 = fmaf(W3[i], h2v[i], o3);

        out[0] = 1.f / (1.f + expf(-o3));
    }
}

// ---------------------------------------------------------------------------
extern "C" void kernel_launch(void* const* d_in, const int* in_sizes, int n_in,
                              void* d_out, int out_size) {
    const float* x  = (const float*)d_in[0];
    const float* es = (const float*)d_in[1];
    const float* iw = (const float*)d_in[2];
    const float* W1 = (const float*)d_in[3];
    const float* b1 = (const float*)d_in[4];
    const float* W2 = (const float*)d_in[5];
    const float* b2 = (const float*)d_in[6];
    const float* W3 = (const float*)d_in[7];
    const float* b3 = (const float*)d_in[8];
    const void*  masks = (const void*)d_in[9];

    ka_assign<<<PP, 512>>>(masks);
    k1_stream<<<dim3(NCHUNK, BB), 256>>>(x);
    k2a_reduce<<<dim3(NGRP, BB), 512>>>();
    k2b_reduce<<<BB, 512>>>();
    k3_parts<<<dim3(PP, BB), 128>>>();
    k4_final<<<1, 128>>>(es, iw, W1, b1, W2, b2, W3, b3, (float*)d_out);
}

// round 5
// speedup vs baseline: 1.4640x; 1.0720x over previous
#include <cuda_runtime.h>
#include <math.h>

// Problem constants (fixed by setup_inputs)
#define BB 8
#define SS 4096
#define DD 512
#define NCHUNK 128
#define SROWS (SS / NCHUNK)   // 32 rows per k1 block
#define NGRP 16               // k2 d-slices of 32
#define PP 98                 // sampled partitions
#define KMAXP 6
#define MAXPART 100
#define MASK_WORDS_PER_P (KMAXP * DD / 4)   // 768 u32 words per partition (u8 view)

// Scratch (no allocations allowed -> __device__ globals)
__device__ float g_partE[NCHUNK * BB * DD];   // 2 MB
__device__ float g_partT[NCHUNK * BB * DD];
__device__ float g_sumE[BB * DD];
__device__ float g_sumT[BB * DD];
__device__ float g_hsP[BB * NGRP];            // per (b,g): sum_d H_sd over 32 d's
__device__ float g_eP [BB * NGRP];            // per (b,g): sum_d SumE
__device__ float g_tP [BB * NGRP];            // per (b,g): sum_d SumT
__device__ float g_hpk[BB * PP];              // per (b,p): sum_k H_pk

// ---------------------------------------------------------------------------
// k1: streaming pass over x. grid = (NCHUNK, B), 256 threads (float2/thread).
// 1024 blocks, ~55 warps/SM to saturate HBM.
// ---------------------------------------------------------------------------
__global__ void __launch_bounds__(256) k1_stream(const float* __restrict__ x) {
    const int chunk = blockIdx.x;
    const int b     = blockIdx.y;
    const int t     = threadIdx.x;

    const float2* xp = reinterpret_cast<const float2*>(
        x + ((size_t)b * SS + (size_t)chunk * SROWS) * DD) + t;

    float e0 = 0.f, e1 = 0.f, t0 = 0.f, t1 = 0.f;
    #pragma unroll 8
    for (int i = 0; i < SROWS; i++) {
        float2 v = xp[(size_t)i * (DD / 2)];
        float p0 = __expf(v.x);
        float p1 = __expf(v.y);
        e0 += p0;
        e1 += p1;
        t0 = fmaf(p0, v.x, t0);
        t1 = fmaf(p1, v.y, t1);
    }

    const int base = (chunk * BB + b) * DD;  // chunk-major for coalesced k2 reads
    reinterpret_cast<float2*>(g_partE + base)[t] = make_float2(e0, e1);
    reinterpret_cast<float2*>(g_partT + base)[t] = make_float2(t0, t1);
}

// ---------------------------------------------------------------------------
// k2: single-stage chunk reduce + per-d singleton entropy + (b,g) partials.
// grid = (NGRP, B) = 128 blocks, 256 threads.
// Thread (seg=t/32, lane=t%32): d = g*32+lane; sums 16 chunks (seg-th slice).
// seg==0 warp finalizes: writes g_sumE/g_sumT, computes h = log(E) - T/E,
// warp-reduces (h, E, T) over its 32 d's -> g_hsP/g_eP/g_tP[b*NGRP+g].
// ---------------------------------------------------------------------------
__global__ void __launch_bounds__(256) k2_reduce() {
    const int g    = blockIdx.x;
    const int b    = blockIdx.y;
    const int t    = threadIdx.x;
    const int seg  = t >> 5;      // 0..7
    const int lane = t & 31;
    const int d    = g * 32 + lane;

    float e = 0.f, tt = 0.f;
    #pragma unroll
    for (int i = 0; i < NCHUNK / 8; i++) {    // 16 chunks per segment
        const int c   = seg * (NCHUNK / 8) + i;
        const int idx = (c * BB + b) * DD + d;
        e  += g_partE[idx];
        tt += g_partT[idx];
    }

    __shared__ float sE[8][32], sT[8][32];
    sE[seg][lane] = e;
    sT[seg][lane] = tt;
    __syncthreads();

    if (seg == 0) {
        float E = 0.f, T = 0.f;
        #pragma unroll
        for (int s = 0; s < 8; s++) { E += sE[s][lane]; T += sT[s][lane]; }
        g_sumE[b * DD + d] = E;
        g_sumT[b * DD + d] = T;

        float h = logf(E) - T / E;            // singleton entropy for (b,d)

        float se = E, st = T, sh = h;
        #pragma unroll
        for (int o = 16; o > 0; o >>= 1) {
            se += __shfl_down_sync(0xffffffffu, se, o);
            st += __shfl_down_sync(0xffffffffu, st, o);
            sh += __shfl_down_sync(0xffffffffu, sh, o);
        }
        if (lane == 0) {
            g_hsP[b * NGRP + g] = sh;
            g_eP [b * NGRP + g] = se;
            g_tP [b * NGRP + g] = st;
        }
    }
}

// ---------------------------------------------------------------------------
// k3: sampled partitions with inline mask decode + per-block dtype detection.
// grid = (P, B), 128 threads x 4 d's.
// Detection: scan this partition's region as u32 words, test byte offset
// ≡1 (mod 4). u8 layout guarantees 128 nonzero hits (one true k per d, for
// every d≡1 mod 4); int32/float32 0/1 layout guarantees zero hits, and the
// scanned range is in-bounds for all candidate dtypes.
// ---------------------------------------------------------------------------
__global__ void __launch_bounds__(128) k3_parts(const void* __restrict__ masks_raw) {
    const int p = blockIdx.x;
    const int b = blockIdx.y;
    const int t = threadIdx.x;
    const unsigned int* mw = (const unsigned int*)masks_raw;

    unsigned int v = 0;
    #pragma unroll
    for (int j = t; j < MASK_WORDS_PER_P; j += 128)
        v |= mw[p * MASK_WORDS_PER_P + j] & 0x0000FF00u;
    const bool isU8 = (__syncthreads_or(v != 0) != 0);

    // part assignment for d = 4t .. 4t+3 (branchless; each d has exactly one k)
    int a0 = 0, a1 = 0, a2 = 0, a3 = 0;
    if (isU8) {
        #pragma unroll
        for (int k = KMAXP - 1; k >= 0; k--) {
            const unsigned int w = mw[(p * KMAXP + k) * (DD / 4) + t]; // 4 bytes = 4 d's
            if (w & 0x000000FFu) a0 = k;
            if (w & 0x0000FF00u) a1 = k;
            if (w & 0x00FF0000u) a2 = k;
            if (w & 0xFF000000u) a3 = k;
        }
    } else {
        const uint4* m4 = (const uint4*)masks_raw;
        #pragma unroll
        for (int k = KMAXP - 1; k >= 0; k--) {
            const uint4 w = m4[(p * KMAXP + k) * (DD / 4) + t];
            if (w.x) a0 = k;
            if (w.y) a1 = k;
            if (w.z) a2 = k;
            if (w.w) a3 = k;
        }
    }

    const float4 e4 = reinterpret_cast<const float4*>(g_sumE + b * DD)[t];
    const float4 t4 = reinterpret_cast<const float4*>(g_sumT + b * DD)[t];

    float zk[KMAXP], tk[KMAXP];
    #pragma unroll
    for (int k = 0; k < KMAXP; k++) {
        zk[k] = (a0 == k ? e4.x : 0.f) + (a1 == k ? e4.y : 0.f)
              + (a2 == k ? e4.z : 0.f) + (a3 == k ? e4.w : 0.f);
        tk[k] = (a0 == k ? t4.x : 0.f) + (a1 == k ? t4.y : 0.f)
              + (a2 == k ? t4.z : 0.f) + (a3 == k ? t4.w : 0.f);
    }

    #pragma unroll
    for (int o = 16; o > 0; o >>= 1) {
        #pragma unroll
        for (int k = 0; k < KMAXP; k++) {
            zk[k] += __shfl_down_sync(0xffffffffu, zk[k], o);
            tk[k] += __shfl_down_sync(0xffffffffu, tk[k], o);
        }
    }
    __shared__ float sz[4][KMAXP], st[4][KMAXP];
    const int w = t >> 5, l = t & 31;
    if (l == 0) {
        #pragma unroll
        for (int k = 0; k < KMAXP; k++) { sz[w][k] = zk[k]; st[w][k] = tk[k]; }
    }
    __syncthreads();
    if (t == 0) {
        float hsum = 0.f;
        #pragma unroll
        for (int k = 0; k < KMAXP; k++) {
            float Z = sz[0][k] + sz[1][k] + sz[2][k] + sz[3][k];
            float T = st[0][k] + st[1][k] + st[2][k] + st[3][k];
            if (Z > 0.f) hsum += logf(Z) - T / Z;   // empty bin -> 0
        }
        g_hpk[b * PP + p] = hsum;
    }
}

// ---------------------------------------------------------------------------
// k4: finalize Hfull/hsingle from (b,g) partials, combine 100 parts,
// min over weighted, MLP head. 1 block, 128 threads.
// ---------------------------------------------------------------------------
__global__ void __launch_bounds__(128) k4_final(
    const float* __restrict__ es,  const float* __restrict__ iw,
    const float* __restrict__ W1,  const float* __restrict__ b1,
    const float* __restrict__ W2,  const float* __restrict__ b2,
    const float* __restrict__ W3,  const float* __restrict__ b3,
    float* __restrict__ out)
{
    __shared__ float sh_min[128];
    __shared__ float sh_es[128];
    __shared__ float shF[BB], shS[BB];
    const int t = threadIdx.x;

    // per-batch Hfull / hsingle from 16 group-partials each
    if (t < BB) {
        float hs = 0.f, E = 0.f, T = 0.f;
        #pragma unroll
        for (int g = 0; g < NGRP; g++) {
            hs += g_hsP[t * NGRP + g];
            E  += g_eP [t * NGRP + g];
            T  += g_tP [t * NGRP + g];
        }
        shS[t] = hs;
        shF[t] = logf(E) - T / E;
    }

    float se = 0.f;
    for (int i = t; i < DD; i += 128) se += es[i];
    sh_es[t] = se;
    __syncthreads();

    float wv = INFINITY;
    if (t < MAXPART) {
        float h;
        if (t == 0) {
            float s = 0.f;
            for (int bb = 0; bb < BB; bb++) s += shF[bb];
            h = s / (float)BB;
        } else if (t == 1) {
            float s = 0.f;
            for (int bb = 0; bb < BB; bb++) s += shS[bb];
            h = s / (float)BB;
        } else {
            float s = 0.f;
            for (int bb = 0; bb < BB; bb++) s += g_hpk[bb * PP + (t - 2)];
            h = s / (float)BB;
        }
        const float sg = 1.f / (1.f + expf(-iw[t]));
        wv = h * sg;
    }
    sh_min[t] = wv;
    __syncthreads();

    #pragma unroll
    for (int o = 64; o > 0; o >>= 1) {
        if (t < o) {
            sh_min[t] = fminf(sh_min[t], sh_min[t + o]);
            sh_es[t] += sh_es[t + o];
        }
        __syncthreads();
    }

    if (t == 0) {
        const float es_mean = sh_es[0] / (float)DD;
        float s = 0.f;
        for (int bb = 0; bb < BB; bb++) s += shF[bb];
        const float h_whole = s / (float)BB;

        const float raw_phi = es_mean * h_whole - sh_min[0];
        float z = raw_phi * 0.1f;
        z = fminf(fmaxf(z, 0.f), 1.f);

        float h1v[32];
        #pragma unroll
        for (int j = 0; j < 32; j++) h1v[j] = fmaxf(fmaf(z, W1[j], b1[j]), 0.f);
        float h2v[16];
        #pragma unroll
        for (int i = 0; i < 16; i++) {
            float a = b2[i];
            #pragma unroll
            for (int j = 0; j < 32; j++) a = fmaf(W2[i * 32 + j], h1v[j], a);
            h2v[i] = fmaxf(a, 0.f);
        }
        float o3 = b3[0];
        #pragma unroll
        for (int i = 0; i < 16; i++) o3 = fmaf(W3[i], h2v[i], o3);

        out[0] = 1.f / (1.f + expf(-o3));
    }
}

// ---------------------------------------------------------------------------
extern "C" void kernel_launch(void* const* d_in, const int* in_sizes, int n_in,
                              void* d_out, int out_size) {
    const float* x  = (const float*)d_in[0];
    const float* es = (const float*)d_in[1];
    const float* iw = (const float*)d_in[2];
    const float* W1 = (const float*)d_in[3];
    const float* b1 = (const float*)d_in[4];
    const float* W2 = (const float*)d_in[5];
    const float* b2 = (const float*)d_in[6];
    const float* W3 = (const float*)d_in[7];
    const float* b3 = (const float*)d_in[8];
    const void*  masks = (const void*)d_in[9];

    k1_stream<<<dim3(NCHUNK, BB), 256>>>(x);
    k2_reduce<<<dim3(NGRP, BB), 256>>>();
    k3_parts<<<dim3(PP, BB), 128>>>(masks);
    k4_final<<<1, 128>>>(es, iw, W1, b1, W2, b2, W3, b3, (float*)d_out);
}

// round 6
// speedup vs baseline: 1.8675x; 1.2756x over previous
#include <cuda_runtime.h>
#include <math.h>

// Problem constants (fixed by setup_inputs)
#define BB 8
#define SS 4096
#define DD 512
#define NCHUNK 128
#define SROWS (SS / NCHUNK)   // 32 rows per k1 block
#define NGRP 16               // k2 d-slices of 32
#define PP 98                 // sampled partitions
#define KMAXP 6
#define MAXPART 100
#define MASK_WORDS_PER_P (KMAXP * DD / 4)   // 768 u32 words per partition (u8 view)

// Scratch (no allocations allowed -> __device__ globals)
__device__ float g_partE[NCHUNK * BB * DD];   // 2 MB
__device__ float g_partT[NCHUNK * BB * DD];
__device__ float g_sumE[BB * DD];
__device__ float g_sumT[BB * DD];
__device__ float g_hsP[BB * NGRP];            // per (b,g): sum_d H_sd over 32 d's
__device__ float g_eP [BB * NGRP];            // per (b,g): sum_d SumE
__device__ float g_tP [BB * NGRP];            // per (b,g): sum_d SumT
__device__ float g_hpk[BB * PP];              // per (b,p): sum_k H_pk

// ---------------------------------------------------------------------------
// k1: streaming pass over x. grid = (NCHUNK, B), 256 threads.
// Thread (sub=t/128, dt=t%128): float4 at column dt of row (2i+sub); 16 iters
// of LDG.128. sub pairs combined in shared before one float4 partial write.
// ---------------------------------------------------------------------------
__global__ void __launch_bounds__(256) k1_stream(const float* __restrict__ x) {
    const int chunk = blockIdx.x;
    const int b     = blockIdx.y;
    const int t     = threadIdx.x;
    const int sub   = t >> 7;     // row parity
    const int dt    = t & 127;    // float4 column

    const float4* xp = reinterpret_cast<const float4*>(
        x + ((size_t)b * SS + (size_t)chunk * SROWS) * DD)
        + (size_t)sub * (DD / 4) + dt;

    float e0 = 0.f, e1 = 0.f, e2 = 0.f, e3 = 0.f;
    float t0 = 0.f, t1 = 0.f, t2 = 0.f, t3 = 0.f;
    #pragma unroll 4
    for (int i = 0; i < SROWS / 2; i++) {
        float4 v = xp[(size_t)i * (DD / 2)];   // advance 2 rows
        float p0 = __expf(v.x), p1 = __expf(v.y), p2 = __expf(v.z), p3 = __expf(v.w);
        e0 += p0; e1 += p1; e2 += p2; e3 += p3;
        t0 = fmaf(p0, v.x, t0);
        t1 = fmaf(p1, v.y, t1);
        t2 = fmaf(p2, v.z, t2);
        t3 = fmaf(p3, v.w, t3);
    }

    __shared__ float4 sE[128], sT[128];
    if (sub == 1) {
        sE[dt] = make_float4(e0, e1, e2, e3);
        sT[dt] = make_float4(t0, t1, t2, t3);
    }
    __syncthreads();
    if (sub == 0) {
        const float4 oe = sE[dt], ot = sT[dt];
        const int base = (chunk * BB + b) * DD;   // chunk-major for k2 reads
        reinterpret_cast<float4*>(g_partE + base)[dt] =
            make_float4(e0 + oe.x, e1 + oe.y, e2 + oe.z, e3 + oe.w);
        reinterpret_cast<float4*>(g_partT + base)[dt] =
            make_float4(t0 + ot.x, t1 + ot.y, t2 + ot.z, t3 + ot.w);
    }
}

// ---------------------------------------------------------------------------
// k2: chunk reduce + per-d singleton entropy + (b,g) partials.
// grid = (NGRP, B) = 128 blocks, 256 threads.
// ---------------------------------------------------------------------------
__global__ void __launch_bounds__(256) k2_reduce() {
    const int g    = blockIdx.x;
    const int b    = blockIdx.y;
    const int t    = threadIdx.x;
    const int seg  = t >> 5;      // 0..7
    const int lane = t & 31;
    const int d    = g * 32 + lane;

    float e = 0.f, tt = 0.f;
    #pragma unroll
    for (int i = 0; i < NCHUNK / 8; i++) {    // 16 chunks per segment
        const int c   = seg * (NCHUNK / 8) + i;
        const int idx = (c * BB + b) * DD + d;
        e  += g_partE[idx];
        tt += g_partT[idx];
    }

    __shared__ float sE[8][32], sT[8][32];
    sE[seg][lane] = e;
    sT[seg][lane] = tt;
    __syncthreads();

    if (seg == 0) {
        float E = 0.f, T = 0.f;
        #pragma unroll
        for (int s = 0; s < 8; s++) { E += sE[s][lane]; T += sT[s][lane]; }
        g_sumE[b * DD + d] = E;
        g_sumT[b * DD + d] = T;

        float h = logf(E) - T / E;            // singleton entropy for (b,d)

        float se = E, st = T, sh = h;
        #pragma unroll
        for (int o = 16; o > 0; o >>= 1) {
            se += __shfl_down_sync(0xffffffffu, se, o);
            st += __shfl_down_sync(0xffffffffu, st, o);
            sh += __shfl_down_sync(0xffffffffu, sh, o);
        }
        if (lane == 0) {
            g_hsP[b * NGRP + g] = sh;
            g_eP [b * NGRP + g] = se;
            g_tP [b * NGRP + g] = st;
        }
    }
}

// ---------------------------------------------------------------------------
// k3: sampled partitions with inline mask decode + per-block dtype detection.
// grid = (P, B), 128 threads x 4 d's. Detection: u8 layout guarantees nonzero
// bytes at offset ≡1 (mod 4) inside this partition's region; int32/float32
// 0/1 layout guarantees all-zero there; range is in-bounds for all dtypes.
// ---------------------------------------------------------------------------
__global__ void __launch_bounds__(128) k3_parts(const void* __restrict__ masks_raw) {
    const int p = blockIdx.x;
    const int b = blockIdx.y;
    const int t = threadIdx.x;
    const unsigned int* mw = (const unsigned int*)masks_raw;

    unsigned int v = 0;
    #pragma unroll
    for (int j = t; j < MASK_WORDS_PER_P; j += 128)
        v |= mw[p * MASK_WORDS_PER_P + j] & 0x0000FF00u;
    const bool isU8 = (__syncthreads_or(v != 0) != 0);

    int a0 = 0, a1 = 0, a2 = 0, a3 = 0;
    if (isU8) {
        #pragma unroll
        for (int k = KMAXP - 1; k >= 0; k--) {
            const unsigned int w = mw[(p * KMAXP + k) * (DD / 4) + t];
            if (w & 0x000000FFu) a0 = k;
            if (w & 0x0000FF00u) a1 = k;
            if (w & 0x00FF0000u) a2 = k;
            if (w & 0xFF000000u) a3 = k;
        }
    } else {
        const uint4* m4 = (const uint4*)masks_raw;
        #pragma unroll
        for (int k = KMAXP - 1; k >= 0; k--) {
            const uint4 w = m4[(p * KMAXP + k) * (DD / 4) + t];
            if (w.x) a0 = k;
            if (w.y) a1 = k;
            if (w.z) a2 = k;
            if (w.w) a3 = k;
        }
    }

    const float4 e4 = reinterpret_cast<const float4*>(g_sumE + b * DD)[t];
    const float4 t4 = reinterpret_cast<const float4*>(g_sumT + b * DD)[t];

    float zk[KMAXP], tk[KMAXP];
    #pragma unroll
    for (int k = 0; k < KMAXP; k++) {
        zk[k] = (a0 == k ? e4.x : 0.f) + (a1 == k ? e4.y : 0.f)
              + (a2 == k ? e4.z : 0.f) + (a3 == k ? e4.w : 0.f);
        tk[k] = (a0 == k ? t4.x : 0.f) + (a1 == k ? t4.y : 0.f)
              + (a2 == k ? t4.z : 0.f) + (a3 == k ? t4.w : 0.f);
    }

    #pragma unroll
    for (int o = 16; o > 0; o >>= 1) {
        #pragma unroll
        for (int k = 0; k < KMAXP; k++) {
            zk[k] += __shfl_down_sync(0xffffffffu, zk[k], o);
            tk[k] += __shfl_down_sync(0xffffffffu, tk[k], o);
        }
    }
    __shared__ float sz[4][KMAXP], st[4][KMAXP];
    const int w = t >> 5, l = t & 31;
    if (l == 0) {
        #pragma unroll
        for (int k = 0; k < KMAXP; k++) { sz[w][k] = zk[k]; st[w][k] = tk[k]; }
    }
    __syncthreads();
    if (t == 0) {
        float hsum = 0.f;
        #pragma unroll
        for (int k = 0; k < KMAXP; k++) {
            float Z = sz[0][k] + sz[1][k] + sz[2][k] + sz[3][k];
            float T = st[0][k] + st[1][k] + st[2][k] + st[3][k];
            if (Z > 0.f) hsum += logf(Z) - T / Z;   // empty bin -> 0
        }
        g_hpk[b * PP + p] = hsum;
    }
}

// ---------------------------------------------------------------------------
// k4: prefetch weights into shared (overlapped with partial loads), finalize
// Hfull/hsingle, min over weighted parts, warp-parallel MLP. 1 block, 128 thr.
// ---------------------------------------------------------------------------
__global__ void __launch_bounds__(128) k4_final(
    const float* __restrict__ es,  const float* __restrict__ iw,
    const float* __restrict__ W1,  const float* __restrict__ b1,
    const float* __restrict__ W2,  const float* __restrict__ b2,
    const float* __restrict__ W3,  const float* __restrict__ b3,
    float* __restrict__ out)
{
    __shared__ float sh_min[128];
    __shared__ float sh_es[128];
    __shared__ float shF[BB], shS[BB];
    __shared__ float sh_w2[16 * 32];
    __shared__ float sh_w1[32], sh_b1[32], sh_b2[16], sh_w3[16], sh_b3;
    __shared__ float sh_h1[32];
    const int t = threadIdx.x;

    // ---- cooperative weight prefetch (issued first; overlaps everything) ----
    reinterpret_cast<float4*>(sh_w2)[t] = reinterpret_cast<const float4*>(W2)[t];
    if (t < 32) { sh_w1[t] = W1[t]; sh_b1[t] = b1[t]; }
    else if (t < 48) { sh_b2[t - 32] = b2[t - 32]; }
    else if (t < 64) { sh_w3[t - 48] = W3[t - 48]; }
    else if (t == 64) { sh_b3 = b3[0]; }

    // per-batch Hfull / hsingle from 16 group-partials each
    if (t >= 96 && t < 96 + BB) {
        const int bb = t - 96;
        float hs = 0.f, E = 0.f, T = 0.f;
        #pragma unroll
        for (int g = 0; g < NGRP; g++) {
            hs += g_hsP[bb * NGRP + g];
            E  += g_eP [bb * NGRP + g];
            T  += g_tP [bb * NGRP + g];
        }
        shS[bb] = hs;
        shF[bb] = logf(E) - T / E;
    }

    float se = 0.f;
    #pragma unroll
    for (int i = 0; i < 4; i++) se += es[t + i * 128];
    sh_es[t] = se;
    __syncthreads();

    float wv = INFINITY;
    if (t < MAXPART) {
        float h;
        if (t == 0) {
            float s = 0.f;
            #pragma unroll
            for (int bb = 0; bb < BB; bb++) s += shF[bb];
            h = s / (float)BB;
        } else if (t == 1) {
            float s = 0.f;
            #pragma unroll
            for (int bb = 0; bb < BB; bb++) s += shS[bb];
            h = s / (float)BB;
        } else {
            float s = 0.f;
            #pragma unroll
            for (int bb = 0; bb < BB; bb++) s += g_hpk[bb * PP + (t - 2)];
            h = s / (float)BB;
        }
        const float sg = 1.f / (1.f + expf(-iw[t]));
        wv = h * sg;
    }
    sh_min[t] = wv;
    __syncthreads();

    #pragma unroll
    for (int o = 64; o > 0; o >>= 1) {
        if (t < o) {
            sh_min[t] = fminf(sh_min[t], sh_min[t + o]);
            sh_es[t] += sh_es[t + o];
        }
        __syncthreads();
    }

    // ---- warp-parallel MLP on warp 0 ----
    if (t < 32) {
        float s = 0.f;
        #pragma unroll
        for (int bb = 0; bb < BB; bb++) s += shF[bb];
        const float h_whole = s / (float)BB;
        const float es_mean = sh_es[0] / (float)DD;

        const float raw_phi = es_mean * h_whole - sh_min[0];
        float z = fminf(fmaxf(raw_phi * 0.1f, 0.f), 1.f);

        sh_h1[t] = fmaxf(fmaf(z, sh_w1[t], sh_b1[t]), 0.f);   // h1, one per lane
        __syncwarp();

        float v = 0.f;
        if (t < 16) {
            float a = sh_b2[t];
            #pragma unroll
            for (int j = 0; j < 32; j++) a = fmaf(sh_w2[t * 32 + j], sh_h1[j], a);
            v = fmaxf(a, 0.f) * sh_w3[t];                      // h2[t] * W3[t]
        }
        #pragma unroll
        for (int o = 16; o > 0; o >>= 1) v += __shfl_down_sync(0xffffffffu, v, o);

        if (t == 0) out[0] = 1.f / (1.f + expf(-(v + sh_b3)));
    }
}

// ---------------------------------------------------------------------------
extern "C" void kernel_launch(void* const* d_in, const int* in_sizes, int n_in,
                              void* d_out, int out_size) {
    const float* x  = (const float*)d_in[0];
    const float* es = (const float*)d_in[1];
    const float* iw = (const float*)d_in[2];
    const float* W1 = (const float*)d_in[3];
    const float* b1 = (const float*)d_in[4];
    const float* W2 = (const float*)d_in[5];
    const float* b2 = (const float*)d_in[6];
    const float* W3 = (const float*)d_in[7];
    const float* b3 = (const float*)d_in[8];
    const void*  masks = (const void*)d_in[9];

    k1_stream<<<dim3(NCHUNK, BB), 256>>>(x);
    k2_reduce<<<dim3(NGRP, BB), 256>>>();
    k3_parts<<<dim3(PP, BB), 128>>>(masks);
    k4_final<<<1, 128>>>(es, iw, W1, b1, W2, b2, W3, b3, (float*)d_out);
}

// round 8
// speedup vs baseline: 1.9345x; 1.0359x over previous
#include <cuda_runtime.h>
#include <math.h>

// Problem constants (fixed by setup_inputs)
#define BB 8
#define SS 4096
#define DD 512
#define NCHUNK 64
#define SROWS (SS / NCHUNK)   // 64 rows per k1 block
#define NGRP 16               // k2 d-slices of 32
#define PP 98                 // sampled partitions
#define KMAXP 6
#define MAXPART 100
#define MASK_WORDS_PER_P (KMAXP * DD / 4)   // 768 u32 words per partition (u8 view)

// Scratch (no allocations allowed -> __device__ globals).
// __align__(16): these are accessed through float4 casts.
__device__ __align__(16) float g_partE[NCHUNK * BB * DD];   // 1 MB
__device__ __align__(16) float g_partT[NCHUNK * BB * DD];
__device__ __align__(16) float g_sumE[BB * DD];
__device__ __align__(16) float g_sumT[BB * DD];
__device__ float g_hsP[BB * NGRP];            // per (b,g): sum_d H_sd over 32 d's
__device__ float g_eP [BB * NGRP];            // per (b,g): sum_d SumE
__device__ float g_tP [BB * NGRP];            // per (b,g): sum_d SumT
__device__ float g_hpk[BB * PP];              // per (b,p): sum_k H_pk
__device__ int   g_cnt = 0;                   // k3 completion counter (self-resetting)

// ---------------------------------------------------------------------------
// k1: streaming pass over x. grid = (NCHUNK, B), 512 threads.
// Thread (sub=t/128, dt=t%128): float4 column dt of rows 4i+sub (16 iters of
// LDG.128). The 4 subs combine in shared; 128 threads write one float4 each.
// 512 blocks x 16 warps = 8192 warps (~55/SM) to saturate HBM.
// ---------------------------------------------------------------------------
__global__ void __launch_bounds__(512) k1_stream(const float* __restrict__ x) {
    const int chunk = blockIdx.x;
    const int b     = blockIdx.y;
    const int t     = threadIdx.x;
    const int sub   = t >> 7;     // 0..3: row subset
    const int dt    = t & 127;    // float4 column

    const float4* xp = reinterpret_cast<const float4*>(
        x + ((size_t)b * SS + (size_t)chunk * SROWS) * DD)
        + (size_t)sub * (DD / 4) + dt;

    float e0 = 0.f, e1 = 0.f, e2 = 0.f, e3 = 0.f;
    float t0 = 0.f, t1 = 0.f, t2 = 0.f, t3 = 0.f;
    #pragma unroll 4
    for (int i = 0; i < SROWS / 4; i++) {
        float4 v = xp[(size_t)i * DD];         // advance 4 rows (= DD float4)
        float p0 = __expf(v.x), p1 = __expf(v.y), p2 = __expf(v.z), p3 = __expf(v.w);
        e0 += p0; e1 += p1; e2 += p2; e3 += p3;
        t0 = fmaf(p0, v.x, t0);
        t1 = fmaf(p1, v.y, t1);
        t2 = fmaf(p2, v.z, t2);
        t3 = fmaf(p3, v.w, t3);
    }

    __shared__ __align__(16) float4 sE[4][128], sT[4][128];
    sE[sub][dt] = make_float4(e0, e1, e2, e3);
    sT[sub][dt] = make_float4(t0, t1, t2, t3);
    __syncthreads();
    if (t < 128) {
        float4 ae = sE[0][t], at = sT[0][t];
        #pragma unroll
        for (int s = 1; s < 4; s++) {
            const float4 oe = sE[s][t], ot = sT[s][t];
            ae.x += oe.x; ae.y += oe.y; ae.z += oe.z; ae.w += oe.w;
            at.x += ot.x; at.y += ot.y; at.z += ot.z; at.w += ot.w;
        }
        const int base = (chunk * BB + b) * DD;   // chunk-major for k2 reads
        reinterpret_cast<float4*>(g_partE + base)[t] = ae;
        reinterpret_cast<float4*>(g_partT + base)[t] = at;
    }
}

// ---------------------------------------------------------------------------
// k2: chunk reduce + per-d singleton entropy + (b,g) partials.
// grid = (NGRP, B) = 128 blocks, 256 threads.
// ---------------------------------------------------------------------------
__global__ void __launch_bounds__(256) k2_reduce() {
    const int g    = blockIdx.x;
    const int b    = blockIdx.y;
    const int t    = threadIdx.x;
    const int seg  = t >> 5;      // 0..7
    const int lane = t & 31;
    const int d    = g * 32 + lane;

    float e = 0.f, tt = 0.f;
    #pragma unroll
    for (int i = 0; i < NCHUNK / 8; i++) {    // 8 chunks per segment
        const int c   = seg * (NCHUNK / 8) + i;
        const int idx = (c * BB + b) * DD + d;
        e  += g_partE[idx];
        tt += g_partT[idx];
    }

    __shared__ float sE[8][32], sT[8][32];
    sE[seg][lane] = e;
    sT[seg][lane] = tt;
    __syncthreads();

    if (seg == 0) {
        float E = 0.f, T = 0.f;
        #pragma unroll
        for (int s = 0; s < 8; s++) { E += sE[s][lane]; T += sT[s][lane]; }
        g_sumE[b * DD + d] = E;
        g_sumT[b * DD + d] = T;

        float h = logf(E) - T / E;            // singleton entropy for (b,d)

        float se = E, st = T, sh = h;
        #pragma unroll
        for (int o = 16; o > 0; o >>= 1) {
            se += __shfl_down_sync(0xffffffffu, se, o);
            st += __shfl_down_sync(0xffffffffu, st, o);
            sh += __shfl_down_sync(0xffffffffu, sh, o);
        }
        if (lane == 0) {
            g_hsP[b * NGRP + g] = sh;
            g_eP [b * NGRP + g] = se;
            g_tP [b * NGRP + g] = st;
        }
    }
}

// ---------------------------------------------------------------------------
// k3: sampled partitions + fused finalize (threadfence-reduction pattern).
// grid = (P, B) = 784 blocks, 128 threads x 4 d's.
// Mask dtype detection per block: u8 layout guarantees nonzero bytes at
// offset ≡1 (mod 4) inside this partition's region; int32/float32 0/1 layout
// guarantees all-zero there; the range is in-bounds for all candidate dtypes.
// After writing g_hpk, blocks fence + count; the last block runs the k4 tail.
// Order-independent -> deterministic. Counter self-resets for graph replays.
// ---------------------------------------------------------------------------
__global__ void __launch_bounds__(128) k3_parts(
    const void*  __restrict__ masks_raw,
    const float* __restrict__ es,  const float* __restrict__ iw,
    const float* __restrict__ W1,  const float* __restrict__ b1,
    const float* __restrict__ W2,  const float* __restrict__ b2,
    const float* __restrict__ W3,  const float* __restrict__ b3,
    float* __restrict__ out)
{
    const int p = blockIdx.x;
    const int b = blockIdx.y;
    const int t = threadIdx.x;
    const unsigned int* mw = (const unsigned int*)masks_raw;

    unsigned int v = 0;
    #pragma unroll
    for (int j = t; j < MASK_WORDS_PER_P; j += 128)
        v |= mw[p * MASK_WORDS_PER_P + j] & 0x0000FF00u;
    const bool isU8 = (__syncthreads_or(v != 0) != 0);

    int a0 = 0, a1 = 0, a2 = 0, a3 = 0;
    if (isU8) {
        #pragma unroll
        for (int k = KMAXP - 1; k >= 0; k--) {
            const unsigned int w = mw[(p * KMAXP + k) * (DD / 4) + t];
            if (w & 0x000000FFu) a0 = k;
            if (w & 0x0000FF00u) a1 = k;
            if (w & 0x00FF0000u) a2 = k;
            if (w & 0xFF000000u) a3 = k;
        }
    } else {
        const uint4* m4 = (const uint4*)masks_raw;
        #pragma unroll
        for (int k = KMAXP - 1; k >= 0; k--) {
            const uint4 w = m4[(p * KMAXP + k) * (DD / 4) + t];
            if (w.x) a0 = k;
            if (w.y) a1 = k;
            if (w.z) a2 = k;
            if (w.w) a3 = k;
        }
    }

    const float4 e4 = reinterpret_cast<const float4*>(g_sumE + b * DD)[t];
    const float4 t4 = reinterpret_cast<const float4*>(g_sumT + b * DD)[t];

    float zk[KMAXP], tk[KMAXP];
    #pragma unroll
    for (int k = 0; k < KMAXP; k++) {
        zk[k] = (a0 == k ? e4.x : 0.f) + (a1 == k ? e4.y : 0.f)
              + (a2 == k ? e4.z : 0.f) + (a3 == k ? e4.w : 0.f);
        tk[k] = (a0 == k ? t4.x : 0.f) + (a1 == k ? t4.y : 0.f)
              + (a2 == k ? t4.z : 0.f) + (a3 == k ? t4.w : 0.f);
    }

    #pragma unroll
    for (int o = 16; o > 0; o >>= 1) {
        #pragma unroll
        for (int k = 0; k < KMAXP; k++) {
            zk[k] += __shfl_down_sync(0xffffffffu, zk[k], o);
            tk[k] += __shfl_down_sync(0xffffffffu, tk[k], o);
        }
    }
    __shared__ float sz[4][KMAXP], sst[4][KMAXP];
    const int w = t >> 5, l = t & 31;
    if (l == 0) {
        #pragma unroll
        for (int k = 0; k < KMAXP; k++) { sz[w][k] = zk[k]; sst[w][k] = tk[k]; }
    }
    __syncthreads();
    if (t == 0) {
        float hsum = 0.f;
        #pragma unroll
        for (int k = 0; k < KMAXP; k++) {
            float Z = sz[0][k] + sz[1][k] + sz[2][k] + sz[3][k];
            float T = sst[0][k] + sst[1][k] + sst[2][k] + sst[3][k];
            if (Z > 0.f) hsum += logf(Z) - T / Z;   // empty bin -> 0
        }
        g_hpk[b * PP + p] = hsum;
    }

    // ---- completion count: is this the last block? ----
    __shared__ int s_last;
    __threadfence();
    __syncthreads();
    if (t == 0) {
        const int old = atomicAdd(&g_cnt, 1);
        s_last = (old == PP * BB - 1);
    }
    __syncthreads();
    if (!s_last) return;

    // ======================= k4 tail (one block) =======================
    __shared__ float sh_min[128];
    __shared__ float sh_es[128];
    __shared__ float shF[BB], shS[BB];
    __shared__ __align__(16) float sh_w2[16 * 32];   // float4-cast target
    __shared__ float sh_w1[32], sh_b1[32], sh_b2[16], sh_w3[16], sh_b3;
    __shared__ float sh_h1[32];

    // cooperative weight prefetch (issued first; overlaps partial loads)
    reinterpret_cast<float4*>(sh_w2)[t] = reinterpret_cast<const float4*>(W2)[t];
    if (t < 32) { sh_w1[t] = W1[t]; sh_b1[t] = b1[t]; }
    else if (t < 48) { sh_b2[t - 32] = b2[t - 32]; }
    else if (t < 64) { sh_w3[t - 48] = W3[t - 48]; }
    else if (t == 64) { sh_b3 = b3[0]; }

    if (t >= 96 && t < 96 + BB) {
        const int bb = t - 96;
        float hs = 0.f, E = 0.f, T = 0.f;
        #pragma unroll
        for (int g = 0; g < NGRP; g++) {
            hs += g_hsP[bb * NGRP + g];
            E  += g_eP [bb * NGRP + g];
            T  += g_tP [bb * NGRP + g];
        }
        shS[bb] = hs;
        shF[bb] = logf(E) - T / E;
    }

    float se = 0.f;
    #pragma unroll
    for (int i = 0; i < 4; i++) se += es[t + i * 128];
    sh_es[t] = se;
    __syncthreads();

    float wv = INFINITY;
    if (t < MAXPART) {
        float h;
        if (t == 0) {
            float s = 0.f;
            #pragma unroll
            for (int bb = 0; bb < BB; bb++) s += shF[bb];
            h = s / (float)BB;
        } else if (t == 1) {
            float s = 0.f;
            #pragma unroll
            for (int bb = 0; bb < BB; bb++) s += shS[bb];
            h = s / (float)BB;
        } else {
            float s = 0.f;
            #pragma unroll
            for (int bb = 0; bb < BB; bb++) s += g_hpk[bb * PP + (t - 2)];
            h = s / (float)BB;
        }
        const float sg = 1.f / (1.f + expf(-iw[t]));
        wv = h * sg;
    }
    sh_min[t] = wv;
    __syncthreads();

    #pragma unroll
    for (int o = 64; o > 0; o >>= 1) {
        if (t < o) {
            sh_min[t] = fminf(sh_min[t], sh_min[t + o]);
            sh_es[t] += sh_es[t + o];
        }
        __syncthreads();
    }

    if (t < 32) {
        float s = 0.f;
        #pragma unroll
        for (int bb = 0; bb < BB; bb++) s += shF[bb];
        const float h_whole = s / (float)BB;
        const float es_mean = sh_es[0] / (float)DD;

        const float raw_phi = es_mean * h_whole - sh_min[0];
        float z = fminf(fmaxf(raw_phi * 0.1f, 0.f), 1.f);

        sh_h1[t] = fmaxf(fmaf(z, sh_w1[t], sh_b1[t]), 0.f);   // h1, one per lane
        __syncwarp();

        float acc = 0.f;
        if (t < 16) {
            float a = sh_b2[t];
            #pragma unroll
            for (int j = 0; j < 32; j++) a = fmaf(sh_w2[t * 32 + j], sh_h1[j], a);
            acc = fmaxf(a, 0.f) * sh_w3[t];                    // h2[t] * W3[t]
        }
        #pragma unroll
        for (int o = 16; o > 0; o >>= 1) acc += __shfl_down_sync(0xffffffffu, acc, o);

        if (t == 0) {
            out[0] = 1.f / (1.f + expf(-(acc + sh_b3)));
            atomicExch(&g_cnt, 0);    // self-reset for the next graph replay
        }
    }
}

// ---------------------------------------------------------------------------
extern "C" void kernel_launch(void* const* d_in, const int* in_sizes, int n_in,
                              void* d_out, int out_size) {
    const float* x  = (const float*)d_in[0];
    const float* es = (const float*)d_in[1];
    const float* iw = (const float*)d_in[2];
    const float* W1 = (const float*)d_in[3];
    const float* b1 = (const float*)d_in[4];
    const float* W2 = (const float*)d_in[5];
    const float* b2 = (const float*)d_in[6];
    const float* W3 = (const float*)d_in[7];
    const float* b3 = (const float*)d_in[8];
    const void*  masks = (const void*)d_in[9];

    k1_stream<<<dim3(NCHUNK, BB), 512>>>(x);
    k2_reduce<<<dim3(NGRP, BB), 256>>>();
    k3_parts<<<dim3(PP, BB), 128>>>(masks, es, iw, W1, b1, W2, b2, W3, b3,
                                    (float*)d_out);
}